// round 11
// baseline (speedup 1.0000x reference)
#include <cuda_runtime.h>
#include <cuda_bf16.h>
#include <cstdint>

#define HID   256
#define LAT   128
#define ODIM  128
#define NBLK  4
#define NIT   10
#define TM    128
#define NTHR  256
#define CLUSTER 2

// SMEM: ctl [0]: tmem ptr; mbarriers: FULL@16/24/32, CM@48/56/64, DONE@80, RDY@88/96/104
#define MB_FULL(s) (16u + (uint32_t)(s) * 8u)
#define MB_CM(s)   (48u + (uint32_t)(s) * 8u)
#define MB_DONE    80u
#define MB_RDY(s)  (88u + (uint32_t)(s) * 8u)
#define SM_Y     1024                    // y: [n/4][m][4] fp32 = 131072 B
#define SM_B     (1024 + 131072)
#define B_SLOT   16384                   // per-CTA N/2 slice of one 32-K stage
#define SM_BYTES (SM_B + 3 * B_SLOT)     // 181248

// TMEM columns (per CTA)
#define TD   0u     // D: this CTA's 128 rows x 256 N fp32
#define TAH  256u   // A hi bf16x2
#define TAL  384u   // A lo bf16x2

// Pre-processed weights: per matrix, stages of 32 K; stage = SMEM image
// N rows x 128B (hi bytes [0,64), lo [64,128)), SW128 swizzled, atom-major.
#define WB_INIT  0u
#define WB_G1(b) (131072u + (unsigned)(b) * 262144u)
#define WB_G2(b) (1179648u + (unsigned)(b) * 262144u)
#define WB_FIN   2228224u
__device__ __align__(128) unsigned char g_wblob[2359296];

// cg2 idesc: M=256 ((256/16)<<24), N<<17/8, f32 acc, bf16 a/b
#define IDESC2_N256 0x10400490u
#define IDESC2_N128 0x10200490u
#define TOTAL_STAGES 652

static constexpr uint64_t DESC_BASE_SW128 =
    (uint64_t(2) << 61) | (uint64_t(1) << 46) | (uint64_t(64) << 32) | (uint64_t(1) << 16);

#if defined(__CUDA_ARCH__) && \
    (defined(__CUDA_ARCH_FEAT_SM103_ALL) || defined(__CUDA_ARCH_FEAT_SM100_ALL) || \
     defined(__CUDA_ARCH_FEAT_SM101_ALL) || defined(__CUDA_ARCH_SPECIFIC__))
#define TC_OK 1
#else
#define TC_OK 0
#endif

static __device__ __forceinline__ uint32_t smem_u32(const void* p) {
    uint32_t a;
    asm("{ .reg .u64 t; cvta.to.shared.u64 t, %1; cvt.u32.u64 %0, t; }" : "=r"(a) : "l"(p));
    return a;
}
static __device__ __forceinline__ uint32_t elect1() {
    uint32_t p;
    asm volatile("{ .reg .pred p; elect.sync _|p, 0xFFFFFFFF; selp.b32 %0, 1, 0, p; }" : "=r"(p));
    return p;
}
static __device__ __forceinline__ uint32_t ctarank() {
    uint32_t r; asm("mov.u32 %0, %%cluster_ctarank;" : "=r"(r)); return r;
}
static __device__ __forceinline__ uint64_t mk_desc(uint32_t addr) {
    return DESC_BASE_SW128 | ((uint64_t)(addr >> 4) & 0x3FFF);
}
static __device__ __forceinline__ uint32_t cvt_bf2(float v0, float v1) {
    uint32_t r;  // lo half = v0, hi half = v1
    asm("cvt.rn.bf16x2.f32 %0, %1, %2;" : "=r"(r) : "f"(v1), "f"(v0));
    return r;
}
static __device__ __forceinline__ float bfu2f(uint32_t us) {
    return __uint_as_float((us & 0xFFFFu) << 16);
}

#define MBAR_INIT(a, n) \
    asm volatile("mbarrier.init.shared.b64 [%0], %1;" :: "r"(a), "r"((uint32_t)(n)) : "memory")
#define MBAR_INVAL(a) \
    asm volatile("mbarrier.inval.shared.b64 [%0];" :: "r"(a) : "memory")
#define MBAR_EXPECT_TX(a, bytes) \
    asm volatile("mbarrier.arrive.expect_tx.shared.b64 _, [%0], %1;" \
                 :: "r"(a), "r"((uint32_t)(bytes)) : "memory")
#define MBAR_WAIT(a, ph) do {                                                          \
    asm volatile("{\n\t.reg .pred P;\nWL_%=:\n\t"                                      \
        "mbarrier.try_wait.parity.acquire.cta.shared::cta.b64 P, [%0], %1, 0x989680;\n\t" \
        "@P bra.uni WD_%=;\n\tbra.uni WL_%=;\nWD_%=:\n\t}"                             \
        :: "r"(a), "r"((uint32_t)(ph)) : "memory");                                    \
} while (0)
// arrive on leader (rank 0) CTA's mbarrier at the same SMEM offset
#define MBAR_ARRIVE_LEADER(a)                                                          \
    asm volatile("{\n\t.reg .b32 ra;\n\tmapa.shared::cluster.u32 ra, %0, 0;\n\t"       \
        "mbarrier.arrive.shared::cluster.b64 _, [ra];\n\t}" :: "r"(a) : "memory")
#define CLUSTER_SYNC() do {                                            \
    asm volatile("barrier.cluster.arrive.aligned;" ::: "memory");      \
    asm volatile("barrier.cluster.wait.aligned;" ::: "memory");        \
} while (0)
static __device__ __forceinline__ void bulk_g2s(uint32_t dst, const void* src,
                                                uint32_t bytes, uint32_t mbar) {
    asm volatile(
        "cp.async.bulk.shared::cluster.global.mbarrier::complete_tx::bytes [%0], [%1], %2, [%3];"
        :: "r"(dst), "l"(src), "r"(bytes), "r"(mbar) : "memory");
}

#if TC_OK
// cg2 TS-mode f16 MMA: A in (each CTA's) TMEM, B split N/2 per CTA SMEM.
static __device__ __forceinline__ void mma_ts2(uint32_t d, uint32_t a, uint64_t bd,
                                               uint32_t idesc, uint32_t en) {
    asm volatile(
        "{\n\t.reg .pred p;\n\tsetp.ne.u32 p, %4, 0;\n\t"
        "tcgen05.mma.cta_group::2.kind::f16 [%0], [%1], %2, %3, "
        "{%5, %5, %5, %5, %5, %5, %5, %5}, p;\n\t}"
        :: "r"(d), "r"(a), "l"(bd), "r"(idesc), "r"(en), "r"(0u) : "memory");
}
#define TC_COMMIT_MC2(mb) \
    asm volatile("tcgen05.commit.cta_group::2.mbarrier::arrive::one.shared::cluster.multicast::cluster.b64 [%0], %1;" \
                 :: "r"(mb), "h"((uint16_t)0x3) : "memory")
#define TC_FENCE_AFTER()   asm volatile("tcgen05.fence::after_thread_sync;" ::: "memory")
#define TC_FENCE_BEFORE()  asm volatile("tcgen05.fence::before_thread_sync;" ::: "memory")
#define TC_WAIT_LD()   asm volatile("tcgen05.wait::ld.sync.aligned;" ::: "memory")
#define TC_WAIT_ST()   asm volatile("tcgen05.wait::st.sync.aligned;" ::: "memory")
#define TC_ALLOC2(sa, n) \
    asm volatile("tcgen05.alloc.cta_group::2.sync.aligned.shared::cta.b32 [%0], %1;" \
                 :: "r"(sa), "r"((uint32_t)(n)) : "memory")
#define TC_DEALLOC2(t, n) \
    asm volatile("tcgen05.dealloc.cta_group::2.sync.aligned.b32 %0, %1;" :: "r"(t), "r"((uint32_t)(n)))
#define TC_RELINQ2() \
    asm volatile("tcgen05.relinquish_alloc_permit.cta_group::2.sync.aligned;")

#define LDTM32(r, a)                                                                    \
    asm volatile("tcgen05.ld.sync.aligned.32x32b.x32.b32 "                              \
        "{%0,%1,%2,%3,%4,%5,%6,%7,%8,%9,%10,%11,%12,%13,%14,%15,"                       \
        "%16,%17,%18,%19,%20,%21,%22,%23,%24,%25,%26,%27,%28,%29,%30,%31}, [%32];"      \
        : "=r"((r)[0]),"=r"((r)[1]),"=r"((r)[2]),"=r"((r)[3]),"=r"((r)[4]),"=r"((r)[5]),\
          "=r"((r)[6]),"=r"((r)[7]),"=r"((r)[8]),"=r"((r)[9]),"=r"((r)[10]),"=r"((r)[11]),\
          "=r"((r)[12]),"=r"((r)[13]),"=r"((r)[14]),"=r"((r)[15]),"=r"((r)[16]),"=r"((r)[17]),\
          "=r"((r)[18]),"=r"((r)[19]),"=r"((r)[20]),"=r"((r)[21]),"=r"((r)[22]),"=r"((r)[23]),\
          "=r"((r)[24]),"=r"((r)[25]),"=r"((r)[26]),"=r"((r)[27]),"=r"((r)[28]),"=r"((r)[29]),\
          "=r"((r)[30]),"=r"((r)[31]) : "r"(a))

#define STTM16(a, r)                                                                    \
    asm volatile("tcgen05.st.sync.aligned.32x32b.x16.b32 [%0], "                        \
        "{%1,%2,%3,%4,%5,%6,%7,%8,%9,%10,%11,%12,%13,%14,%15,%16};"                     \
        :: "r"(a), "r"((r)[0]),"r"((r)[1]),"r"((r)[2]),"r"((r)[3]),"r"((r)[4]),"r"((r)[5]),\
           "r"((r)[6]),"r"((r)[7]),"r"((r)[8]),"r"((r)[9]),"r"((r)[10]),"r"((r)[11]),   \
           "r"((r)[12]),"r"((r)[13]),"r"((r)[14]),"r"((r)[15]) : "memory")

#define STTM32(a, r)                                                                    \
    asm volatile("tcgen05.st.sync.aligned.32x32b.x32.b32 [%0], "                        \
        "{%1,%2,%3,%4,%5,%6,%7,%8,%9,%10,%11,%12,%13,%14,%15,%16,"                      \
        "%17,%18,%19,%20,%21,%22,%23,%24,%25,%26,%27,%28,%29,%30,%31,%32};"             \
        :: "r"(a), "r"((r)[0]),"r"((r)[1]),"r"((r)[2]),"r"((r)[3]),"r"((r)[4]),"r"((r)[5]),\
           "r"((r)[6]),"r"((r)[7]),"r"((r)[8]),"r"((r)[9]),"r"((r)[10]),"r"((r)[11]),   \
           "r"((r)[12]),"r"((r)[13]),"r"((r)[14]),"r"((r)[15]),"r"((r)[16]),"r"((r)[17]),\
           "r"((r)[18]),"r"((r)[19]),"r"((r)[20]),"r"((r)[21]),"r"((r)[22]),"r"((r)[23]),\
           "r"((r)[24]),"r"((r)[25]),"r"((r)[26]),"r"((r)[27]),"r"((r)[28]),"r"((r)[29]),\
           "r"((r)[30]),"r"((r)[31]) : "memory")
#else
static __device__ __forceinline__ void mma_ts2(uint32_t, uint32_t, uint64_t, uint32_t, uint32_t) {}
#define TC_COMMIT_MC2(mb)  do { (void)(mb); } while (0)
#define TC_FENCE_AFTER()   do {} while (0)
#define TC_FENCE_BEFORE()  do {} while (0)
#define TC_WAIT_LD()       do {} while (0)
#define TC_WAIT_ST()       do {} while (0)
#define TC_ALLOC2(sa, n)   do { (void)(sa); (void)(n); } while (0)
#define TC_DEALLOC2(t, n)  do { (void)(t); (void)(n); } while (0)
#define TC_RELINQ2()       do {} while (0)
#define LDTM32(r, a)       do { _Pragma("unroll") for (int _i = 0; _i < 32; _i++) (r)[_i] = 0u; (void)(a); } while (0)
#define STTM16(a, r)       do { (void)(a); (void)(r); } while (0)
#define STTM32(a, r)       do { (void)(a); (void)(r); } while (0)
#endif

// stage index -> (full-stage blob ptr, per-CTA half bytes)
static __device__ __forceinline__ void stage_info(int i, const unsigned char** p, uint32_t* half) {
    if (i < 4) { *p = g_wblob + WB_INIT + (size_t)i * 32768; *half = 16384u; return; }
    i -= 4;
    if (i < 640) {
        int gg = i >> 3, s = i & 7;
        int b = gg / 20, r = gg % 20;
        unsigned base = (r & 1) ? WB_G2(b) : WB_G1(b);
        *p = g_wblob + base + (size_t)s * 32768; *half = 16384u; return;
    }
    i -= 640;
    *p = g_wblob + WB_FIN + (size_t)i * 16384; *half = 8192u;
}

// ---------------- merged weight prep ----------------
__global__ void prep_all(const float* __restrict__ Wi, const float* __restrict__ Wg1,
                         const float* __restrict__ Wg2, const float* __restrict__ Wf) {
    int gid = blockIdx.x * blockDim.x + threadIdx.x;
    if (gid >= 589824) return;
    const float* W; int N; unsigned off; int e;
    if (gid < 32768)       { W = Wi; N = HID; off = WB_INIT; e = gid; }
    else if (gid < 294912) { int j = gid - 32768;  int b = j >> 16; e = j & 65535;
                             W = Wg1 + (size_t)b * 65536; N = HID; off = WB_G1(b); }
    else if (gid < 557056) { int j = gid - 294912; int b = j >> 16; e = j & 65535;
                             W = Wg2 + (size_t)b * 65536; N = HID; off = WB_G2(b); }
    else                   { e = gid - 557056; W = Wf; N = ODIM; off = WB_FIN; }
    int k = e / N, n = e % N;
    float w = W[e];
    __nv_bfloat16 hb = __float2bfloat16(w);
    float hf = __bfloat162float(hb);
    __nv_bfloat16 lb = __float2bfloat16(w - hf);
    int stage = k >> 5, kl = k & 31;
    unsigned row = (unsigned)((n >> 3) * 1024 + (n & 7) * 128);
    unsigned oh = row + kl * 2;
    unsigned ol = row + (32 + kl) * 2;
    oh ^= (oh >> 3) & 0x70;
    ol ^= (ol >> 3) & 0x70;
    unsigned char* sb = g_wblob + off + (size_t)stage * ((size_t)N * 128);
    *(unsigned short*)(sb + oh) = *reinterpret_cast<unsigned short*>(&hb);
    *(unsigned short*)(sb + ol) = *reinterpret_cast<unsigned short*>(&lb);
}

// ---------------- GEMM driver (cg2): leader issues MMA, both CTAs feed B ----------------
static __device__ void do_gemm(uint32_t smb, uint32_t tmem, int base, int nst, uint32_t idesc,
                               int g, uint32_t& fph, uint32_t& cph, uint32_t& rph,
                               uint32_t& pend, uint32_t rank) {
    if ((threadIdx.x >> 5) == 0 && elect1()) {
        TC_FENCE_AFTER();
        for (int c = 0; c < nst; c++) {
            int idx = base + c;
            int s = idx % 3;
            MBAR_WAIT(smb + MB_FULL(s), (fph >> s) & 1);
            fph ^= 1u << s;
            MBAR_ARRIVE_LEADER(smb + MB_RDY(s));   // my B half is ready
            if (rank == 0) {
                MBAR_WAIT(smb + MB_RDY(s), (rph >> s) & 1);  // both halves ready
                rph ^= 1u << s;
                uint64_t bd = mk_desc(smb + SM_B + (uint32_t)s * B_SLOT);
#pragma unroll
                for (int s2 = 0; s2 < 2; s2++) {
                    uint32_t ks = (uint32_t)(c * 2 + s2);
                    uint32_t ah = tmem + TAH + ks * 8;
                    uint32_t al = tmem + TAL + ks * 8;
                    uint32_t bo = (uint32_t)(s2 * 2);
                    mma_ts2(tmem + TD, ah, bd + bo,     idesc, (uint32_t)((c | s2) != 0));
                    mma_ts2(tmem + TD, al, bd + bo,     idesc, 1u);
                    mma_ts2(tmem + TD, ah, bd + bo + 4, idesc, 1u);
                }
                TC_COMMIT_MC2(smb + MB_CM(s));
                if (c == nst - 1) TC_COMMIT_MC2(smb + MB_DONE);
            }
            pend |= 1u << s;
            int nx = idx + 2;
            if (nx < TOTAL_STAGES) {
                int sx = nx % 3;
                if ((pend >> sx) & 1) {
                    MBAR_WAIT(smb + MB_CM(sx), (cph >> sx) & 1);  // slot consumed (multicast)
                    cph ^= 1u << sx;
                }
                const unsigned char* p; uint32_t half;
                stage_info(nx, &p, &half);
                MBAR_EXPECT_TX(smb + MB_FULL(sx), half);
                bulk_g2s(smb + SM_B + (uint32_t)sx * B_SLOT, p + (size_t)rank * half,
                         half, smb + MB_FULL(sx));
            }
        }
    }
    MBAR_WAIT(smb + MB_DONE, g & 1);
    TC_FENCE_AFTER();
}

// process one 32-col D chunk: bias/activation/y, split to bf16 hi/lo, store to TMEM A
static __device__ __forceinline__ void proc_chunk(char* sm, uint32_t tmem,
        const float* __restrict__ bias, int mode, int wy, int m, int n0, uint32_t* d) {
    float v[32];
#pragma unroll
    for (int q = 0; q < 8; q++) {
        float4 bq = ((const float4*)(bias + n0))[q];
        v[q*4+0] = __uint_as_float(d[q*4+0]) + bq.x;
        v[q*4+1] = __uint_as_float(d[q*4+1]) + bq.y;
        v[q*4+2] = __uint_as_float(d[q*4+2]) + bq.z;
        v[q*4+3] = __uint_as_float(d[q*4+3]) + bq.w;
    }
    if (mode == 1) {
#pragma unroll
        for (int i = 0; i < 32; i++) v[i] = fmaxf(v[i], 0.0f);
    } else if (mode == 2) {
#pragma unroll
        for (int q = 0; q < 8; q++) {
            float4 yq = *(const float4*)(sm + SM_Y + (size_t)((n0 >> 2) + q) * 2048 + (size_t)m * 16);
            v[q*4+0] = yq.x - v[q*4+0];
            v[q*4+1] = yq.y - v[q*4+1];
            v[q*4+2] = yq.z - v[q*4+2];
            v[q*4+3] = yq.w - v[q*4+3];
        }
    }
    if (wy) {
#pragma unroll
        for (int q = 0; q < 8; q++)
            *(float4*)(sm + SM_Y + (size_t)((n0 >> 2) + q) * 2048 + (size_t)m * 16) =
                make_float4(v[q*4+0], v[q*4+1], v[q*4+2], v[q*4+3]);
    }
    uint32_t hi[16], lo[16];
#pragma unroll
    for (int p = 0; p < 16; p++) {
        float a0 = v[2*p], a1 = v[2*p+1];
        uint32_t hh = cvt_bf2(a0, a1);
        float l0 = a0 - bfu2f(hh);
        float l1 = a1 - bfu2f(hh >> 16);
        hi[p] = hh;
        lo[p] = cvt_bf2(l0, l1);
    }
    STTM16(tmem + TAH + (uint32_t)(n0 >> 1), hi);
    STTM16(tmem + TAL + (uint32_t)(n0 >> 1), lo);
}

// epilogue (hidden, N=256): mode 0: v=d+b; 1: relu; 2: y-(d+b). wy: also store v into y.
static __device__ void epi_hidden(char* sm, uint32_t tmem, const float* __restrict__ bias,
                                  int mode, int wy) {
    const int tid = threadIdx.x, w = tid >> 5, lane = tid & 31;
    const int m = (w & 3) * 32 + lane, h = w >> 2;
#pragma unroll 1
    for (int tt = 0; tt < 2; tt++) {
        int n0 = h * 128 + tt * 64;
        uint32_t d0[32], d1[32];
        LDTM32(d0, tmem + TD + (uint32_t)n0);
        LDTM32(d1, tmem + TD + (uint32_t)(n0 + 32));
        TC_WAIT_LD();
        proc_chunk(sm, tmem, bias, mode, wy, m, n0, d0);
        proc_chunk(sm, tmem, bias, mode, wy, m, n0 + 32, d1);
    }
    TC_WAIT_ST();
    TC_FENCE_BEFORE();
    CLUSTER_SYNC();   // both CTAs' A in TMEM visible before leader issues next MMA
}

static __device__ void build_initA(const float* __restrict__ x, uint32_t tmem, int row_base) {
    const int tid = threadIdx.x, w = tid >> 5, lane = tid & 31;
    const int m = (w & 3) * 32 + lane, khalf = w >> 2;
    const int k0 = khalf * 64;
    const float4* xr = (const float4*)(x + (size_t)(row_base + m) * LAT + k0);
    float xv[64];
#pragma unroll
    for (int j = 0; j < 16; j++) {
        float4 q = xr[j];
        xv[j*4+0] = q.x; xv[j*4+1] = q.y; xv[j*4+2] = q.z; xv[j*4+3] = q.w;
    }
    uint32_t hi[32], lo[32];
#pragma unroll
    for (int p = 0; p < 32; p++) {
        float a0 = xv[2*p], a1 = xv[2*p+1];
        uint32_t hh = cvt_bf2(a0, a1);
        float l0 = a0 - bfu2f(hh);
        float l1 = a1 - bfu2f(hh >> 16);
        hi[p] = hh;
        lo[p] = cvt_bf2(l0, l1);
    }
    STTM32(tmem + TAH + (uint32_t)(khalf * 32), hi);
    STTM32(tmem + TAL + (uint32_t)(khalf * 32), lo);
    TC_WAIT_ST();
    TC_FENCE_BEFORE();
    CLUSTER_SYNC();
}

static __device__ void epi_final(uint32_t tmem, const float* __restrict__ bias,
                                 float* __restrict__ out, int row_base) {
    const int tid = threadIdx.x, w = tid >> 5, lane = tid & 31;
    const int m = (w & 3) * 32 + lane, h = w >> 2;
    int n0 = h * 64;
    uint32_t d0[32], d1[32];
    LDTM32(d0, tmem + TD + (uint32_t)n0);
    LDTM32(d1, tmem + TD + (uint32_t)(n0 + 32));
    TC_WAIT_LD();
#pragma unroll 1
    for (int half = 0; half < 2; half++) {
        uint32_t* d = half ? d1 : d0;
        int nb = n0 + half * 32;
        float* orow = out + (size_t)(row_base + m) * ODIM + nb;
#pragma unroll
        for (int q = 0; q < 8; q++) {
            float4 bq = ((const float4*)(bias + nb))[q];
            float4 o;
            o.x = __uint_as_float(d[q*4+0]) + bq.x;
            o.y = __uint_as_float(d[q*4+1]) + bq.y;
            o.z = __uint_as_float(d[q*4+2]) + bq.z;
            o.w = __uint_as_float(d[q*4+3]) + bq.w;
            *(float4*)(orow + q * 4) = o;
        }
    }
}

__global__ void __launch_bounds__(NTHR, 1) __cluster_dims__(CLUSTER, 1, 1)
inv_main(const float* __restrict__ x,
         const float* __restrict__ b_init, const float* __restrict__ bg1,
         const float* __restrict__ bg2,    const float* __restrict__ b_final,
         float* __restrict__ out) {
    extern __shared__ __align__(1024) char sm[];
    const uint32_t smb = smem_u32(sm);
    const int tid = threadIdx.x;
    const uint32_t rank = ctarank();
    const int row_base = blockIdx.x * TM;

    if (tid == 0) {
#pragma unroll
        for (int s = 0; s < 3; s++) {
            MBAR_INIT(smb + MB_FULL(s), 1);
            MBAR_INIT(smb + MB_CM(s), 1);
            MBAR_INIT(smb + MB_RDY(s), 2);   // both CTAs arrive per stage
        }
        MBAR_INIT(smb + MB_DONE, 1);
    }
    if ((tid >> 5) == 0) { TC_ALLOC2(smb, 512); TC_RELINQ2(); }
    __syncthreads();
    uint32_t tmem;
    asm volatile("ld.shared.b32 %0, [%1];" : "=r"(tmem) : "r"(smb));

    uint32_t fph = 0, cph = 0, rph = 0, pend = 0;

    // bootstrap: stages 0,1 (my half) into slots 0,1
    if ((tid >> 5) == 0 && elect1()) {
#pragma unroll
        for (int i = 0; i < 2; i++) {
            const unsigned char* p; uint32_t half;
            stage_info(i, &p, &half);
            MBAR_EXPECT_TX(smb + MB_FULL(i), half);
            bulk_g2s(smb + SM_B + (uint32_t)i * B_SLOT, p + (size_t)rank * half,
                     half, smb + MB_FULL(i));
        }
    }

    build_initA(x, tmem, row_base);   // ends with CLUSTER_SYNC (also orders mbarrier init)

    int g = 0, base = 0;
    do_gemm(smb, tmem, base, 4, IDESC2_N256, g, fph, cph, rph, pend, rank);
    g++; base += 4;
    epi_hidden(sm, tmem, b_init, 0, 1);

    for (int b = 0; b < NBLK; b++) {
        const float* b1 = bg1 + b * HID;
        const float* b2 = bg2 + b * HID;
        for (int it = 0; it < NIT; it++) {
            do_gemm(smb, tmem, base, 8, IDESC2_N256, g, fph, cph, rph, pend, rank);
            g++; base += 8;
            epi_hidden(sm, tmem, b1, 1, 0);
            do_gemm(smb, tmem, base, 8, IDESC2_N256, g, fph, cph, rph, pend, rank);
            g++; base += 8;
            epi_hidden(sm, tmem, b2, 2, (it == NIT - 1) ? 1 : 0);
        }
    }

    do_gemm(smb, tmem, base, 8, IDESC2_N128, g, fph, cph, rph, pend, rank);
    epi_final(tmem, b_final, out, row_base);

    __syncthreads();
    if (tid == 0) {
#pragma unroll
        for (int s = 0; s < 3; s++) {
            MBAR_INVAL(smb + MB_FULL(s)); MBAR_INVAL(smb + MB_CM(s)); MBAR_INVAL(smb + MB_RDY(s));
        }
        MBAR_INVAL(smb + MB_DONE);
    }
    __syncthreads();
    if ((tid >> 5) == 0) { TC_RELINQ2(); TC_DEALLOC2(tmem, 512); }
    CLUSTER_SYNC();   // no CTA exits while peer ops may target it
}

extern "C" void kernel_launch(void* const* d_in, const int* in_sizes, int n_in,
                              void* d_out, int out_size) {
    const float* x       = (const float*)d_in[0];
    const float* W_init  = (const float*)d_in[1];
    const float* b_init  = (const float*)d_in[2];
    const float* Wg1     = (const float*)d_in[3];
    const float* bg1     = (const float*)d_in[4];
    const float* Wg2     = (const float*)d_in[5];
    const float* bg2     = (const float*)d_in[6];
    const float* W_final = (const float*)d_in[7];
    const float* b_final = (const float*)d_in[8];
    float* out = (float*)d_out;

    const int batch = in_sizes[0] / LAT;

    prep_all<<<(589824 + 255) / 256, 256>>>(W_init, Wg1, Wg2, W_final);

    cudaFuncSetAttribute(inv_main, cudaFuncAttributeMaxDynamicSharedMemorySize, SM_BYTES);
    inv_main<<<batch / TM, NTHR, SM_BYTES>>>(x, b_init, bg1, bg2, b_final, out);
}

// round 13
// speedup vs baseline: 1.3855x; 1.3855x over previous
#include <cuda_runtime.h>
#include <cuda_bf16.h>
#include <cstdint>

#define HID   256
#define LAT   128
#define ODIM  128
#define NBLK  4
#define NIT   10
#define TM    128
#define NTHR  256

// SMEM: [0] tmem ptr; mbarriers: FULL@16/24/32, CM@48/56/64, DONE@80, ARDY[8]@96..152
#define MB_FULL(s) (16u + (uint32_t)(s) * 8u)
#define MB_CM(s)   (48u + (uint32_t)(s) * 8u)
#define MB_DONE    80u
#define MB_ARDY(s) (96u + (uint32_t)(s) * 8u)
#define SM_Y     1024                    // y: [n/4][m][4] fp32 = 131072 B
#define SM_B     (1024 + 131072)
#define B_SLOT   32768
#define SM_BYTES (SM_B + 3 * B_SLOT)     // 230400

// TMEM: two 256-col regions, ping-pong D/A per GEMM parity.
// A layout (interleaved): k-block j (32 k): hi bf16x2 @ base+32j..+15, lo @ base+32j+16..+31.

#define WB_INIT  0u
#define WB_G1(b) (131072u + (unsigned)(b) * 262144u)
#define WB_G2(b) (1179648u + (unsigned)(b) * 262144u)
#define WB_FIN   2228224u
__device__ __align__(128) unsigned char g_wblob[2359296];

#define IDESC_N256 0x8400490u
#define IDESC_N128 0x8200490u
#define TOTAL_STAGES 652
#define NGEMM 82

static constexpr uint64_t DESC_BASE_SW128 =
    (uint64_t(2) << 61) | (uint64_t(1) << 46) | (uint64_t(64) << 32) | (uint64_t(1) << 16);

#if defined(__CUDA_ARCH__) && \
    (defined(__CUDA_ARCH_FEAT_SM103_ALL) || defined(__CUDA_ARCH_FEAT_SM100_ALL) || \
     defined(__CUDA_ARCH_FEAT_SM101_ALL) || defined(__CUDA_ARCH_SPECIFIC__))
#define TC_OK 1
#else
#define TC_OK 0
#endif

static __device__ __forceinline__ uint32_t smem_u32(const void* p) {
    uint32_t a;
    asm("{ .reg .u64 t; cvta.to.shared.u64 t, %1; cvt.u32.u64 %0, t; }" : "=r"(a) : "l"(p));
    return a;
}
static __device__ __forceinline__ uint32_t elect1() {
    uint32_t p;
    asm volatile("{ .reg .pred p; elect.sync _|p, 0xFFFFFFFF; selp.b32 %0, 1, 0, p; }" : "=r"(p));
    return p;
}
static __device__ __forceinline__ uint64_t mk_desc(uint32_t addr) {
    return DESC_BASE_SW128 | ((uint64_t)(addr >> 4) & 0x3FFF);
}
static __device__ __forceinline__ uint32_t cvt_bf2(float v0, float v1) {
    uint32_t r;
    asm("cvt.rn.bf16x2.f32 %0, %1, %2;" : "=r"(r) : "f"(v1), "f"(v0));
    return r;
}
static __device__ __forceinline__ float bfu2f(uint32_t us) {
    return __uint_as_float((us & 0xFFFFu) << 16);
}

#define MBAR_INIT(a, n) \
    asm volatile("mbarrier.init.shared.b64 [%0], %1;" :: "r"(a), "r"((uint32_t)(n)) : "memory")
#define MBAR_INVAL(a) \
    asm volatile("mbarrier.inval.shared.b64 [%0];" :: "r"(a) : "memory")
#define MBAR_ARRIVE(a) \
    asm volatile("mbarrier.arrive.shared.b64 _, [%0];" :: "r"(a) : "memory")
#define MBAR_EXPECT_TX(a, bytes) \
    asm volatile("mbarrier.arrive.expect_tx.shared.b64 _, [%0], %1;" \
                 :: "r"(a), "r"((uint32_t)(bytes)) : "memory")
#define MBAR_WAIT(a, ph) do {                                                          \
    asm volatile("{\n\t.reg .pred P;\nWL_%=:\n\t"                                      \
        "mbarrier.try_wait.parity.acquire.cta.shared::cta.b64 P, [%0], %1, 0x989680;\n\t" \
        "@P bra.uni WD_%=;\n\tbra.uni WL_%=;\nWD_%=:\n\t}"                             \
        :: "r"(a), "r"((uint32_t)(ph)) : "memory");                                    \
} while (0)
static __device__ __forceinline__ void bulk_g2s(uint32_t dst, const void* src,
                                                uint32_t bytes, uint32_t mbar) {
    asm volatile(
        "cp.async.bulk.shared::cluster.global.mbarrier::complete_tx::bytes [%0], [%1], %2, [%3];"
        :: "r"(dst), "l"(src), "r"(bytes), "r"(mbar) : "memory");
}

#if TC_OK
static __device__ __forceinline__ void mma_ts(uint32_t d, uint32_t a, uint64_t bd,
                                              uint32_t idesc, uint32_t en) {
    asm volatile(
        "{\n\t.reg .pred p;\n\tsetp.ne.u32 p, %4, 0;\n\t"
        "tcgen05.mma.cta_group::1.kind::f16 [%0], [%1], %2, %3, {%5, %5, %5, %5}, p;\n\t}"
        :: "r"(d), "r"(a), "l"(bd), "r"(idesc), "r"(en), "r"(0u) : "memory");
}
#define TC_COMMIT(mb) \
    asm volatile("tcgen05.commit.cta_group::1.mbarrier::arrive::one.shared::cluster.b64 [%0];" \
                 :: "r"(mb) : "memory")
#define TC_FENCE_AFTER()   asm volatile("tcgen05.fence::after_thread_sync;" ::: "memory")
#define TC_FENCE_BEFORE()  asm volatile("tcgen05.fence::before_thread_sync;" ::: "memory")
#define TC_WAIT_LD()   asm volatile("tcgen05.wait::ld.sync.aligned;" ::: "memory")
#define TC_WAIT_ST()   asm volatile("tcgen05.wait::st.sync.aligned;" ::: "memory")
#define TC_ALLOC(sa, n) \
    asm volatile("tcgen05.alloc.cta_group::1.sync.aligned.shared::cta.b32 [%0], %1;" \
                 :: "r"(sa), "r"((uint32_t)(n)) : "memory")
#define TC_DEALLOC(t, n) \
    asm volatile("tcgen05.dealloc.cta_group::1.sync.aligned.b32 %0, %1;" :: "r"(t), "r"((uint32_t)(n)))
#define TC_RELINQ() \
    asm volatile("tcgen05.relinquish_alloc_permit.cta_group::1.sync.aligned;")

#define LDTM32(r, a)                                                                    \
    asm volatile("tcgen05.ld.sync.aligned.32x32b.x32.b32 "                              \
        "{%0,%1,%2,%3,%4,%5,%6,%7,%8,%9,%10,%11,%12,%13,%14,%15,"                       \
        "%16,%17,%18,%19,%20,%21,%22,%23,%24,%25,%26,%27,%28,%29,%30,%31}, [%32];"      \
        : "=r"((r)[0]),"=r"((r)[1]),"=r"((r)[2]),"=r"((r)[3]),"=r"((r)[4]),"=r"((r)[5]),\
          "=r"((r)[6]),"=r"((r)[7]),"=r"((r)[8]),"=r"((r)[9]),"=r"((r)[10]),"=r"((r)[11]),\
          "=r"((r)[12]),"=r"((r)[13]),"=r"((r)[14]),"=r"((r)[15]),"=r"((r)[16]),"=r"((r)[17]),\
          "=r"((r)[18]),"=r"((r)[19]),"=r"((r)[20]),"=r"((r)[21]),"=r"((r)[22]),"=r"((r)[23]),\
          "=r"((r)[24]),"=r"((r)[25]),"=r"((r)[26]),"=r"((r)[27]),"=r"((r)[28]),"=r"((r)[29]),\
          "=r"((r)[30]),"=r"((r)[31]) : "r"(a))

#define STTM16(a, r)                                                                    \
    asm volatile("tcgen05.st.sync.aligned.32x32b.x16.b32 [%0], "                        \
        "{%1,%2,%3,%4,%5,%6,%7,%8,%9,%10,%11,%12,%13,%14,%15,%16};"                     \
        :: "r"(a), "r"((r)[0]),"r"((r)[1]),"r"((r)[2]),"r"((r)[3]),"r"((r)[4]),"r"((r)[5]),\
           "r"((r)[6]),"r"((r)[7]),"r"((r)[8]),"r"((r)[9]),"r"((r)[10]),"r"((r)[11]),   \
           "r"((r)[12]),"r"((r)[13]),"r"((r)[14]),"r"((r)[15]) : "memory")
#else
static __device__ __forceinline__ void mma_ts(uint32_t, uint32_t, uint64_t, uint32_t, uint32_t) {}
#define TC_COMMIT(mb)      do { (void)(mb); } while (0)
#define TC_FENCE_AFTER()   do {} while (0)
#define TC_FENCE_BEFORE()  do {} while (0)
#define TC_WAIT_LD()       do {} while (0)
#define TC_WAIT_ST()       do {} while (0)
#define TC_ALLOC(sa, n)    do { (void)(sa); (void)(n); } while (0)
#define TC_DEALLOC(t, n)   do { (void)(t); (void)(n); } while (0)
#define TC_RELINQ()        do {} while (0)
#define LDTM32(r, a)       do { _Pragma("unroll") for (int _i = 0; _i < 32; _i++) (r)[_i] = 0u; (void)(a); } while (0)
#define STTM16(a, r)       do { (void)(a); (void)(r); } while (0)
#endif

static __device__ __forceinline__ void stage_info(int i, const unsigned char** p, uint32_t* nb) {
    if (i < 4) { *p = g_wblob + WB_INIT + (size_t)i * 32768; *nb = 32768u; return; }
    i -= 4;
    if (i < 640) {
        int gg = i >> 3, s = i & 7;
        int b = gg / 20, r = gg % 20;
        unsigned base = (r & 1) ? WB_G2(b) : WB_G1(b);
        *p = g_wblob + base + (size_t)s * 32768; *nb = 32768u; return;
    }
    i -= 640;
    *p = g_wblob + WB_FIN + (size_t)i * 16384; *nb = 16384u;
}

__global__ void prep_all(const float* __restrict__ Wi, const float* __restrict__ Wg1,
                         const float* __restrict__ Wg2, const float* __restrict__ Wf) {
    int gid = blockIdx.x * blockDim.x + threadIdx.x;
    if (gid >= 589824) return;
    const float* W; int N; unsigned off; int e;
    if (gid < 32768)       { W = Wi; N = HID; off = WB_INIT; e = gid; }
    else if (gid < 294912) { int j = gid - 32768;  int b = j >> 16; e = j & 65535;
                             W = Wg1 + (size_t)b * 65536; N = HID; off = WB_G1(b); }
    else if (gid < 557056) { int j = gid - 294912; int b = j >> 16; e = j & 65535;
                             W = Wg2 + (size_t)b * 65536; N = HID; off = WB_G2(b); }
    else                   { e = gid - 557056; W = Wf; N = ODIM; off = WB_FIN; }
    int k = e / N, n = e % N;
    float w = W[e];
    __nv_bfloat16 hb = __float2bfloat16(w);
    float hf = __bfloat162float(hb);
    __nv_bfloat16 lb = __float2bfloat16(w - hf);
    int stage = k >> 5, kl = k & 31;
    unsigned row = (unsigned)((n >> 3) * 1024 + (n & 7) * 128);
    unsigned oh = row + kl * 2;
    unsigned ol = row + (32 + kl) * 2;
    oh ^= (oh >> 3) & 0x70;
    ol ^= (ol >> 3) & 0x70;
    unsigned char* sb = g_wblob + off + (size_t)stage * ((size_t)N * 128);
    *(unsigned short*)(sb + oh) = *reinterpret_cast<unsigned short*>(&hb);
    *(unsigned short*)(sb + ol) = *reinterpret_cast<unsigned short*>(&lb);
}

// ---------------- driver warp: B ring + MMA issue for all 82 GEMMs ----------------
static __device__ void driver(uint32_t smb, uint32_t tmem) {
    if (!elect1()) return;
    // bootstrap slots 0,1
#pragma unroll
    for (int i = 0; i < 2; i++) {
        const unsigned char* p; uint32_t nb;
        stage_info(i, &p, &nb);
        MBAR_EXPECT_TX(smb + MB_FULL(i), nb);
        bulk_g2s(smb + SM_B + (uint32_t)i * B_SLOT, p, nb, smb + MB_FULL(i));
    }
    uint32_t fph = 0, cph = 0, pend = 0, aph = 0;
    int base = 0;
    for (int g = 0; g < NGEMM; g++) {
        const int nst = (g == 0) ? 4 : 8;
        const uint32_t idesc = (g == NGEMM - 1) ? IDESC_N128 : IDESC_N256;
        const uint32_t dbase = (uint32_t)(g & 1) * 256u;
        const uint32_t abase = dbase ^ 256u;
        for (int c = 0; c < nst; c++) {
            int idx = base + c;
            int s = idx % 3;
            MBAR_WAIT(smb + MB_FULL(s), (fph >> s) & 1);
            fph ^= 1u << s;
            MBAR_WAIT(smb + MB_ARDY(c), (aph >> c) & 1);  // A chunk c of this gen ready
            aph ^= 1u << c;
            TC_FENCE_AFTER();
            uint64_t bd = mk_desc(smb + SM_B + (uint32_t)s * B_SLOT);
#pragma unroll
            for (int s2 = 0; s2 < 2; s2++) {
                uint32_t ah = tmem + abase + (uint32_t)(32 * c) + (uint32_t)(s2 * 8);
                uint32_t al = ah + 16u;
                uint32_t bo = (uint32_t)(s2 * 2);
                mma_ts(tmem + dbase, ah, bd + bo,     idesc, (uint32_t)((c | s2) != 0));
                mma_ts(tmem + dbase, al, bd + bo,     idesc, 1u);
                mma_ts(tmem + dbase, ah, bd + bo + 4, idesc, 1u);
            }
            TC_COMMIT(smb + MB_CM(s));
            pend |= 1u << s;
            if (c == nst - 1) TC_COMMIT(smb + MB_DONE);
            int nx = idx + 2;
            if (nx < TOTAL_STAGES) {
                int sx = nx % 3;
                if ((pend >> sx) & 1) {
                    MBAR_WAIT(smb + MB_CM(sx), (cph >> sx) & 1);
                    cph ^= 1u << sx;
                }
                const unsigned char* p; uint32_t nb;
                stage_info(nx, &p, &nb);
                MBAR_EXPECT_TX(smb + MB_FULL(sx), nb);
                bulk_g2s(smb + SM_B + (uint32_t)sx * B_SLOT, p, nb, smb + MB_FULL(sx));
            }
        }
        base += nst;
    }
}

// ---------------- worker warps 0-3 ----------------
// one 32-col chunk: bias/act/y, split, STTM into the same cols (A of next gen)
static __device__ __forceinline__ void proc_chunk(char* sm, uint32_t tmem, uint32_t dbase,
        const float* __restrict__ bias, int mode, int wy, int m, int j, uint32_t* d) {
    const int n0 = 32 * j;
    float v[32];
#pragma unroll
    for (int q = 0; q < 8; q++) {
        float4 bq = ((const float4*)(bias + n0))[q];
        v[q*4+0] = __uint_as_float(d[q*4+0]) + bq.x;
        v[q*4+1] = __uint_as_float(d[q*4+1]) + bq.y;
        v[q*4+2] = __uint_as_float(d[q*4+2]) + bq.z;
        v[q*4+3] = __uint_as_float(d[q*4+3]) + bq.w;
    }
    if (mode == 1) {
#pragma unroll
        for (int i = 0; i < 32; i++) v[i] = fmaxf(v[i], 0.0f);
    } else if (mode == 2) {
#pragma unroll
        for (int q = 0; q < 8; q++) {
            float4 yq = *(const float4*)(sm + SM_Y + (size_t)((n0 >> 2) + q) * 2048 + (size_t)m * 16);
            v[q*4+0] = yq.x - v[q*4+0];
            v[q*4+1] = yq.y - v[q*4+1];
            v[q*4+2] = yq.z - v[q*4+2];
            v[q*4+3] = yq.w - v[q*4+3];
        }
    }
    if (wy) {
#pragma unroll
        for (int q = 0; q < 8; q++)
            *(float4*)(sm + SM_Y + (size_t)((n0 >> 2) + q) * 2048 + (size_t)m * 16) =
                make_float4(v[q*4+0], v[q*4+1], v[q*4+2], v[q*4+3]);
    }
    uint32_t hi[16], lo[16];
#pragma unroll
    for (int p = 0; p < 16; p++) {
        float a0 = v[2*p], a1 = v[2*p+1];
        uint32_t hh = cvt_bf2(a0, a1);
        hi[p] = hh;
        lo[p] = cvt_bf2(a0 - bfu2f(hh), a1 - bfu2f(hh >> 16));
    }
    STTM16(tmem + dbase + (uint32_t)n0, hi);
    STTM16(tmem + dbase + (uint32_t)n0 + 16u, lo);
}

static __device__ void epi_hidden(char* sm, uint32_t smb, uint32_t tmem, uint32_t dbase,
                                  const float* __restrict__ bias, int mode, int wy, int m) {
#pragma unroll 1
    for (int pp = 0; pp < 4; pp++) {
        int j0 = 2 * pp;
        uint32_t d0[32], d1[32];
        LDTM32(d0, tmem + dbase + (uint32_t)(32 * j0));
        LDTM32(d1, tmem + dbase + (uint32_t)(32 * j0 + 32));
        TC_WAIT_LD();
        proc_chunk(sm, tmem, dbase, bias, mode, wy, m, j0,     d0);
        proc_chunk(sm, tmem, dbase, bias, mode, wy, m, j0 + 1, d1);
        TC_WAIT_ST();
        TC_FENCE_BEFORE();
        if (elect1()) {
            MBAR_ARRIVE(smb + MB_ARDY(j0));
            MBAR_ARRIVE(smb + MB_ARDY(j0 + 1));
        }
    }
}

static __device__ void build_initA(const float* __restrict__ x, uint32_t smb, uint32_t tmem,
                                   int row_base, int m) {
    const float4* xr = (const float4*)(x + (size_t)(row_base + m) * LAT);
#pragma unroll 1
    for (int blk = 0; blk < 4; blk++) {
        float xv[32];
#pragma unroll
        for (int q = 0; q < 8; q++) {
            float4 t = xr[blk * 8 + q];
            xv[q*4+0] = t.x; xv[q*4+1] = t.y; xv[q*4+2] = t.z; xv[q*4+3] = t.w;
        }
        uint32_t hi[16], lo[16];
#pragma unroll
        for (int p = 0; p < 16; p++) {
            float a0 = xv[2*p], a1 = xv[2*p+1];
            uint32_t hh = cvt_bf2(a0, a1);
            hi[p] = hh;
            lo[p] = cvt_bf2(a0 - bfu2f(hh), a1 - bfu2f(hh >> 16));
        }
        STTM16(tmem + 256u + (uint32_t)(32 * blk), hi);
        STTM16(tmem + 256u + (uint32_t)(32 * blk) + 16u, lo);
    }
    TC_WAIT_ST();
    TC_FENCE_BEFORE();
    if (elect1()) {
#pragma unroll
        for (int s = 0; s < 4; s++) MBAR_ARRIVE(smb + MB_ARDY(s));
    }
}

static __device__ void epi_final(uint32_t tmem, const float* __restrict__ bias,
                                 float* __restrict__ out, int row_base, int m) {
    const uint32_t dbase = 256u;   // g=81 odd
#pragma unroll 1
    for (int pp = 0; pp < 2; pp++) {
        int n0 = 64 * pp;
        uint32_t d0[32], d1[32];
        LDTM32(d0, tmem + dbase + (uint32_t)n0);
        LDTM32(d1, tmem + dbase + (uint32_t)(n0 + 32));
        TC_WAIT_LD();
#pragma unroll
        for (int half = 0; half < 2; half++) {
            uint32_t* d = half ? d1 : d0;
            int nb = n0 + half * 32;
            float* orow = out + (size_t)(row_base + m) * ODIM + nb;
#pragma unroll
            for (int q = 0; q < 8; q++) {
                float4 bq = ((const float4*)(bias + nb))[q];
                float4 o;
                o.x = __uint_as_float(d[q*4+0]) + bq.x;
                o.y = __uint_as_float(d[q*4+1]) + bq.y;
                o.z = __uint_as_float(d[q*4+2]) + bq.z;
                o.w = __uint_as_float(d[q*4+3]) + bq.w;
                *(float4*)(orow + q * 4) = o;
            }
        }
    }
}

__global__ void __launch_bounds__(NTHR, 1)
inv_main(const float* __restrict__ x,
         const float* __restrict__ b_init, const float* __restrict__ bg1,
         const float* __restrict__ bg2,    const float* __restrict__ b_final,
         float* __restrict__ out) {
    extern __shared__ __align__(1024) char sm[];
    const uint32_t smb = smem_u32(sm);
    const int tid = threadIdx.x, wid = tid >> 5, lane = tid & 31;
    const int row_base = blockIdx.x * TM;

    if (tid == 0) {
#pragma unroll
        for (int s = 0; s < 3; s++) { MBAR_INIT(smb + MB_FULL(s), 1); MBAR_INIT(smb + MB_CM(s), 1); }
        MBAR_INIT(smb + MB_DONE, 1);
#pragma unroll
        for (int s = 0; s < 8; s++) MBAR_INIT(smb + MB_ARDY(s), 4);
    }
    if (wid == 0) { TC_ALLOC(smb, 512); TC_RELINQ(); }
    __syncthreads();
    uint32_t tmem;
    asm volatile("ld.shared.b32 %0, [%1];" : "=r"(tmem) : "r"(smb));

    if (wid == 4) {
        driver(smb, tmem);
    } else if (wid < 4) {
        const int m = wid * 32 + lane;
        build_initA(x, smb, tmem, row_base, m);
        int eph = 0;
        // epilogue 0 (after init GEMM, g=0, D@0)
        MBAR_WAIT(smb + MB_DONE, eph); eph ^= 1;
        TC_FENCE_AFTER();
        epi_hidden(sm, smb, tmem, 0u, b_init, 0, 1, m);
        int g = 1;
        for (int b = 0; b < NBLK; b++) {
            const float* b1 = bg1 + b * HID;
            const float* b2 = bg2 + b * HID;
            for (int it = 0; it < NIT; it++) {
                MBAR_WAIT(smb + MB_DONE, eph); eph ^= 1;
                TC_FENCE_AFTER();
                epi_hidden(sm, smb, tmem, (uint32_t)(g & 1) * 256u, b1, 1, 0, m);
                g++;
                MBAR_WAIT(smb + MB_DONE, eph); eph ^= 1;
                TC_FENCE_AFTER();
                epi_hidden(sm, smb, tmem, (uint32_t)(g & 1) * 256u, b2, 2,
                           (it == NIT - 1) ? 1 : 0, m);
                g++;
            }
        }
        MBAR_WAIT(smb + MB_DONE, eph); eph ^= 1;   // final GEMM (g=81)
        TC_FENCE_AFTER();
        epi_final(tmem, b_final, out, row_base, m);
    }
    // warps 5-7 fall through

    __syncthreads();
    if (tid == 0) {
#pragma unroll
        for (int s = 0; s < 3; s++) { MBAR_INVAL(smb + MB_FULL(s)); MBAR_INVAL(smb + MB_CM(s)); }
        MBAR_INVAL(smb + MB_DONE);
#pragma unroll
        for (int s = 0; s < 8; s++) MBAR_INVAL(smb + MB_ARDY(s));
    }
    __syncthreads();
    if (wid == 0) { TC_DEALLOC(tmem, 512); }
}

extern "C" void kernel_launch(void* const* d_in, const int* in_sizes, int n_in,
                              void* d_out, int out_size) {
    const float* x       = (const float*)d_in[0];
    const float* W_init  = (const float*)d_in[1];
    const float* b_init  = (const float*)d_in[2];
    const float* Wg1     = (const float*)d_in[3];
    const float* bg1     = (const float*)d_in[4];
    const float* Wg2     = (const float*)d_in[5];
    const float* bg2     = (const float*)d_in[6];
    const float* W_final = (const float*)d_in[7];
    const float* b_final = (const float*)d_in[8];
    float* out = (float*)d_out;

    const int batch = in_sizes[0] / LAT;

    prep_all<<<(589824 + 255) / 256, 256>>>(W_init, Wg1, Wg2, W_final);

    cudaFuncSetAttribute(inv_main, cudaFuncAttributeMaxDynamicSharedMemorySize, SM_BYTES);
    inv_main<<<batch / TM, NTHR, SM_BYTES>>>(x, b_init, bg1, bg2, b_final, out);
}